// round 2
// baseline (speedup 1.0000x reference)
#include <cuda_runtime.h>

#define NMOL 1024
#define MOLSIZE 128
#define MAXP 8128          // 128*127/2 upper-triangle max per molecule

// ---- static device scratch (no runtime allocation allowed) ----
__device__ int            g_atomCnt[NMOL];
__device__ int            g_pairCnt[NMOL];
__device__ int            g_atomBase[NMOL];
__device__ int            g_pairBase[NMOL];
__device__ int            g_nReal;
__device__ int            g_nPairs;
__device__ unsigned short g_pairList[NMOL * MAXP];   // (a<<8)|b, row-major order per molecule

// d2 threshold replicating (sqrtf(d2) < 5.0f): largest excluded d2 is 25-1ulp,
// because sqrtf(25 - 1ulp) rounds to exactly 5.0f.
__device__ __forceinline__ float d2_thresh() { return __int_as_float(0x41C7FFFF); }

// ============================================================================
// K1: per-molecule stats + ordered per-molecule close-pair list + counts
// ============================================================================
__global__ void __launch_bounds__(MOLSIZE)
k_count(const int* __restrict__ species, const float* __restrict__ coords,
        const float* __restrict__ tore, float* __restrict__ out)
{
    __shared__ float4 sc[MOLSIZE];
    __shared__ int    ssp[MOLSIZE];
    __shared__ int    sWI[4][3];     // per-warp: heavy, hydro, nonblank
    __shared__ float  sWF[4];        // per-warp: sum tore[sp]
    __shared__ int    sWC[4];        // per-warp inclusive pair-count totals

    const int m    = blockIdx.x;
    const int a    = threadIdx.x;
    const int lane = a & 31;
    const int wid  = a >> 5;

    const int sp = species[m * MOLSIZE + a];
    ssp[a] = sp;
    const float* cp = coords + (size_t)(m * MOLSIZE + a) * 3;
    const float x = cp[0], y = cp[1], z = cp[2];
    sc[a] = make_float4(x, y, z, 0.0f);

    // ---- per-molecule stats (warp + block reduce) ----
    int   heavy = (sp > 1), hydro = (sp == 1), nbv = (sp > 0);
    float tv = tore[sp];
    int h1 = heavy, h2 = hydro, h3 = nbv; float f1 = tv;
    #pragma unroll
    for (int o = 16; o; o >>= 1) {
        h1 += __shfl_down_sync(0xffffffffu, h1, o);
        h2 += __shfl_down_sync(0xffffffffu, h2, o);
        h3 += __shfl_down_sync(0xffffffffu, h3, o);
        f1 += __shfl_down_sync(0xffffffffu, f1, o);
    }
    if (lane == 0) { sWI[wid][0] = h1; sWI[wid][1] = h2; sWI[wid][2] = h3; sWF[wid] = f1; }
    __syncthreads();
    if (a == 0) {
        int H = 0, Y = 0, N = 0; float F = 0.0f;
        #pragma unroll
        for (int w = 0; w < 4; w++) { H += sWI[w][0]; Y += sWI[w][1]; N += sWI[w][2]; F += sWF[w]; }
        out[2 + m]            = (float)H;            // nHeavy
        out[2 + NMOL + m]     = (float)Y;            // nHydro
        out[2 + 2*NMOL + m]   = (float)(int)(F * 0.5f); // nocc (trunc, exact: tore ints)
        g_atomCnt[m] = N;
        if (m == 0) { out[0] = (float)NMOL; out[1] = (float)MOLSIZE; }
    }

    // ---- close-pair predicate over row a (b > a), bitmask per 32-b word ----
    const int nbflag = (sp > 0);
    unsigned acc[4];
    int cnt = 0;
    #pragma unroll
    for (int w = 0; w < 4; w++) {
        unsigned accw = 0u;
        if (nbflag && (w * 32 + 31) > a) {
            const int b0 = w * 32;
            #pragma unroll 8
            for (int b = b0; b < b0 + 32; b++) {
                if (b > a && ssp[b] > 0) {
                    float4 pb = sc[b];
                    float dx = pb.x - x, dy = pb.y - y, dz = pb.z - z;
                    float d2 = dx * dx + dy * dy + dz * dz;
                    if (d2 < d2_thresh()) accw |= 1u << (b - b0);
                }
            }
        }
        acc[w] = accw;
        cnt += __popc(accw);
    }

    // ---- ordered intra-molecule exclusive scan of row counts ----
    int incl = cnt;
    #pragma unroll
    for (int o = 1; o < 32; o <<= 1) {
        int v = __shfl_up_sync(0xffffffffu, incl, o);
        if (lane >= o) incl += v;
    }
    if (lane == 31) sWC[wid] = incl;
    __syncthreads();
    int wbase = 0;
    #pragma unroll
    for (int w = 0; w < 4; w++) if (w < wid) wbase += sWC[w];
    const int excl  = wbase + incl - cnt;
    if (a == 0) g_pairCnt[m] = sWC[0] + sWC[1] + sWC[2] + sWC[3];

    // ---- emit (a,b) list in order ----
    unsigned short* dst = g_pairList + m * MAXP + excl;
    int k = 0;
    #pragma unroll
    for (int w = 0; w < 4; w++) {
        unsigned mm = acc[w];
        while (mm) {
            int b = (w << 5) + __ffs((int)mm) - 1;
            mm &= mm - 1u;
            dst[k++] = (unsigned short)((a << 8) | b);
        }
    }
}

// ============================================================================
// K2: exclusive scans across molecules (single block, 1024 threads)
// ============================================================================
__global__ void __launch_bounds__(NMOL)
k_scan()
{
    __shared__ int s[NMOL];
    const int t = threadIdx.x;

    int v = g_atomCnt[t];
    s[t] = v; __syncthreads();
    for (int o = 1; o < NMOL; o <<= 1) {
        int x = (t >= o) ? s[t - o] : 0;
        __syncthreads();
        s[t] += x;
        __syncthreads();
    }
    g_atomBase[t] = s[t] - v;
    if (t == NMOL - 1) g_nReal = s[t];
    __syncthreads();

    int w = g_pairCnt[t];
    s[t] = w; __syncthreads();
    for (int o = 1; o < NMOL; o <<= 1) {
        int x = (t >= o) ? s[t - o] : 0;
        __syncthreads();
        s[t] += x;
        __syncthreads();
    }
    g_pairBase[t] = s[t] - w;
    if (t == NMOL - 1) g_nPairs = s[t];
}

// ============================================================================
// K3: scatter all atom-level and pair-level outputs
// ============================================================================
__global__ void __launch_bounds__(256)
k_write(const int* __restrict__ species, const float* __restrict__ coords,
        float* __restrict__ out)
{
    __shared__ float4 sc[MOLSIZE];
    __shared__ int    ssp[MOLSIZE];
    __shared__ int    srank[MOLSIZE];
    __shared__ int    sW[8];

    const int m    = blockIdx.x;
    const int tid  = threadIdx.x;
    const int lane = tid & 31;
    const int wid  = tid >> 5;

    int nb = 0, sp = 0;
    if (tid < MOLSIZE) {
        sp = species[m * MOLSIZE + tid];
        ssp[tid] = sp;
        const float* cp = coords + (size_t)(m * MOLSIZE + tid) * 3;
        sc[tid] = make_float4(cp[0], cp[1], cp[2], 0.0f);
        nb = (sp > 0);
    }
    unsigned bal = __ballot_sync(0xffffffffu, nb);
    if (lane == 0) sW[wid] = __popc(bal);
    __syncthreads();

    const int nReal = g_nReal;
    if (tid < MOLSIZE) {
        int wbase = 0;
        #pragma unroll
        for (int w = 0; w < 4; w++) if (w < wid) wbase += sW[w];
        const int rank = g_atomBase[m] + wbase + __popc(bal & ((1u << lane) - 1u));
        srank[tid] = rank;
        if (nb) {
            out[3074 + rank]             = (float)sp;                          // Z
            out[3074 + nReal + rank]     = (float)(tid * (MOLSIZE + 1) + m * MOLSIZE * MOLSIZE); // maskd
            out[3074 + 2 * nReal + rank] = (float)m;                           // atom_molid
        }
    }
    __syncthreads();

    const int nP   = g_nPairs;
    const int base = g_pairBase[m];
    const int cnt  = g_pairCnt[m];
    const int P0   = 3074 + 3 * nReal;
    const unsigned short* pl = g_pairList + m * MAXP;

    for (int t = tid; t < cnt; t += 256) {
        const int ab = pl[t];
        const int a = ab >> 8, b = ab & 255;
        float4 pa = sc[a], pb = sc[b];
        float dx = pb.x - pa.x, dy = pb.y - pa.y, dz = pb.z - pa.z;
        float d2   = dx * dx + dy * dy + dz * dz;
        float dist = sqrtf(d2);
        const int q = base + t;
        out[P0 + q]           = (float)(m * (MOLSIZE * MOLSIZE) + a * MOLSIZE + b); // mask
        out[P0 + nP + q]      = (float)m;            // pair_molid
        out[P0 + 2 * nP + q]  = (float)ssp[a];       // ni
        out[P0 + 3 * nP + q]  = (float)ssp[b];       // nj
        out[P0 + 4 * nP + q]  = (float)srank[a];     // idxi
        out[P0 + 5 * nP + q]  = (float)srank[b];     // idxj
        out[P0 + 6 * nP + 3 * q + 0] = dx / dist;    // xij
        out[P0 + 6 * nP + 3 * q + 1] = dy / dist;
        out[P0 + 6 * nP + 3 * q + 2] = dz / dist;
        out[P0 + 9 * nP + q]  = dist * 1.8897261258369282f; // rij
    }
}

// ============================================================================
extern "C" void kernel_launch(void* const* d_in, const int* in_sizes, int n_in,
                              void* d_out, int out_size)
{
    const int*   species = (const int*)d_in[0];
    const float* coords  = (const float*)d_in[1];
    const float* tore    = (const float*)d_in[2];
    float*       out     = (float*)d_out;
    (void)in_sizes; (void)n_in; (void)out_size;

    k_count<<<NMOL, MOLSIZE>>>(species, coords, tore, out);
    k_scan<<<1, NMOL>>>();
    k_write<<<NMOL, 256>>>(species, coords, out);
}

// round 3
// speedup vs baseline: 1.1724x; 1.1724x over previous
#include <cuda_runtime.h>

#define NMOL 1024
#define MOLSIZE 128
#define MAXP 8128          // 128*127/2 upper-triangle max per molecule
#define MPB 2              // molecules per k_count block
#define CNT_GRID (NMOL / MPB)

// ---- static device scratch (no runtime allocation allowed) ----
__device__ int            g_atomCnt[NMOL];
__device__ int            g_pairCnt[NMOL];
__device__ int            g_atomBase[NMOL];
__device__ int            g_pairBase[NMOL];
__device__ int            g_nReal;
__device__ int            g_nPairs;
__device__ int            g_ticket = 0;
__device__ unsigned short g_pairList[NMOL * MAXP];   // (a<<8)|b, row-major per molecule

// d2 threshold replicating (sqrtf(d2) < 5.0f): largest excluded d2 is 25-1ulp.
__device__ __forceinline__ float d2_thresh() { return __int_as_float(0x41C7FFFF); }

// ============================================================================
// K1: stats + ordered close-pair lists (half-matrix) + fused global scan
// ============================================================================
__global__ void __launch_bounds__(256)
k_count(const int* __restrict__ species, const float* __restrict__ coords,
        const float* __restrict__ tore, float* __restrict__ out)
{
    __shared__ float4   sc[MPB][MOLSIZE];
    __shared__ unsigned rowmask[MPB][MOLSIZE][4];
    __shared__ unsigned nbw[MPB][4];
    __shared__ int      sWI[8][3];
    __shared__ float    sWF[8];
    __shared__ int      sWC[8];
    __shared__ int      sScanA[8], sScanB[8];
    __shared__ int      sLast;

    const int tid  = threadIdx.x;
    const int ml   = tid >> 7;          // local molecule 0/1
    const int a    = tid & 127;
    const int lane = tid & 31;
    const int wid  = tid >> 5;          // 0..7
    const int gw   = wid & 3;           // warp within 128-thread group
    const int m    = blockIdx.x * MPB + ml;

    const int sp = species[m * MOLSIZE + a];
    const float* cp = coords + (size_t)(m * MOLSIZE + a) * 3;
    const float x = cp[0], y = cp[1], z = cp[2];
    sc[ml][a] = make_float4(x, y, z, 0.0f);

    rowmask[ml][a][0] = 0u; rowmask[ml][a][1] = 0u;
    rowmask[ml][a][2] = 0u; rowmask[ml][a][3] = 0u;

    // ---- per-molecule stats (warp reduce, combine per group) ----
    int   h1 = (sp > 1), h2 = (sp == 1), h3 = (sp > 0);
    float f1 = tore[sp];
    #pragma unroll
    for (int o = 16; o; o >>= 1) {
        h1 += __shfl_down_sync(0xffffffffu, h1, o);
        h2 += __shfl_down_sync(0xffffffffu, h2, o);
        h3 += __shfl_down_sync(0xffffffffu, h3, o);
        f1 += __shfl_down_sync(0xffffffffu, f1, o);
    }
    if (lane == 0) { sWI[wid][0] = h1; sWI[wid][1] = h2; sWI[wid][2] = h3; sWF[wid] = f1; }
    const unsigned bal = __ballot_sync(0xffffffffu, sp > 0);
    if (lane == 0) nbw[ml][gw] = bal;
    __syncthreads();
    if (a == 0) {
        int H = 0, Y = 0, N = 0; float F = 0.0f;
        #pragma unroll
        for (int w = 0; w < 4; w++) {
            H += sWI[ml*4+w][0]; Y += sWI[ml*4+w][1]; N += sWI[ml*4+w][2]; F += sWF[ml*4+w];
        }
        out[2 + m]          = (float)H;               // nHeavy
        out[2 + NMOL + m]   = (float)Y;               // nHydro
        out[2 + 2*NMOL + m] = (float)(int)(F * 0.5f); // nocc
        g_atomCnt[m] = N;
        if (m == 0) { out[0] = (float)NMOL; out[1] = (float)MOLSIZE; }
    }

    // ---- circular half-matrix distance tests: pair (a, (a+o)&127), o=1..64 ----
    #pragma unroll 4
    for (int o = 1; o < 64; o++) {
        const int b = (a + o) & 127;
        float4 pb = sc[ml][b];
        float dx = pb.x - x, dy = pb.y - y, dz = pb.z - z;
        float d2 = dx*dx + dy*dy + dz*dz;
        if (d2 < d2_thresh()) {
            const int i = a < b ? a : b;
            const int j = a ^ b ^ i;
            atomicOr(&rowmask[ml][i][j >> 5], 1u << (j & 31));
        }
    }
    if (a < 64) {                       // o = 64 half-diagonal
        const int b = a + 64;
        float4 pb = sc[ml][b];
        float dx = pb.x - x, dy = pb.y - y, dz = pb.z - z;
        float d2 = dx*dx + dy*dy + dz*dz;
        if (d2 < d2_thresh())
            atomicOr(&rowmask[ml][a][b >> 5], 1u << (b & 31));
    }
    __syncthreads();

    // ---- apply nonblank mask, count ----
    const unsigned own = (nbw[ml][a >> 5] >> (a & 31)) & 1u;
    unsigned r[4];
    int cnt = 0;
    #pragma unroll
    for (int w = 0; w < 4; w++) {
        r[w] = own ? (rowmask[ml][a][w] & nbw[ml][w]) : 0u;
        cnt += __popc(r[w]);
    }

    // ---- ordered intra-molecule exclusive scan of row counts ----
    int incl = cnt;
    #pragma unroll
    for (int o = 1; o < 32; o <<= 1) {
        int v = __shfl_up_sync(0xffffffffu, incl, o);
        if (lane >= o) incl += v;
    }
    if (lane == 31) sWC[wid] = incl;
    __syncthreads();
    int wbase = 0;
    #pragma unroll
    for (int w = 0; w < 4; w++) if (w < gw) wbase += sWC[ml*4 + w];
    const int excl = wbase + incl - cnt;
    if (a == 0)
        g_pairCnt[m] = sWC[ml*4] + sWC[ml*4+1] + sWC[ml*4+2] + sWC[ml*4+3];

    // ---- emit (a,b) list in row-major order ----
    unsigned short* dst = g_pairList + m * MAXP + excl;
    int k = 0;
    #pragma unroll
    for (int w = 0; w < 4; w++) {
        unsigned mm = r[w];
        while (mm) {
            int b = (w << 5) + __ffs((int)mm) - 1;
            mm &= mm - 1u;
            dst[k++] = (unsigned short)((a << 8) | b);
        }
    }

    // ---- fused global scan: last block to finish scans all 1024 counts ----
    __syncthreads();
    if (tid == 0) {
        __threadfence();
        int old = atomicAdd(&g_ticket, 1);
        sLast = (old == (int)gridDim.x - 1);
    }
    __syncthreads();
    if (sLast) {
        const int b4 = tid * 4;
        int oA[4], oB[4], sA = 0, sB = 0;
        #pragma unroll
        for (int q = 0; q < 4; q++) {
            oA[q] = g_atomCnt[b4 + q]; sA += oA[q];
            oB[q] = g_pairCnt[b4 + q]; sB += oB[q];
        }
        int ia = sA, ib = sB;
        #pragma unroll
        for (int o = 1; o < 32; o <<= 1) {
            int va = __shfl_up_sync(0xffffffffu, ia, o);
            int vb = __shfl_up_sync(0xffffffffu, ib, o);
            if (lane >= o) { ia += va; ib += vb; }
        }
        if (lane == 31) { sScanA[wid] = ia; sScanB[wid] = ib; }
        __syncthreads();
        int bA = 0, bB = 0;
        #pragma unroll
        for (int w = 0; w < 8; w++) if (w < wid) { bA += sScanA[w]; bB += sScanB[w]; }
        int pA = bA + ia - sA, pB = bB + ib - sB;
        #pragma unroll
        for (int q = 0; q < 4; q++) {
            g_atomBase[b4 + q] = pA; pA += oA[q];
            g_pairBase[b4 + q] = pB; pB += oB[q];
        }
        if (tid == 255) { g_nReal = pA; g_nPairs = pB; }
        if (tid == 0)   g_ticket = 0;    // reset for next graph replay
    }
}

// ============================================================================
// K2: scatter all atom-level and pair-level outputs
// ============================================================================
__global__ void __launch_bounds__(256)
k_write(const int* __restrict__ species, const float* __restrict__ coords,
        float* __restrict__ out)
{
    __shared__ float4 sc[MOLSIZE];
    __shared__ int    ssp[MOLSIZE];
    __shared__ int    srank[MOLSIZE];
    __shared__ int    sW[8];

    const int m    = blockIdx.x;
    const int tid  = threadIdx.x;
    const int lane = tid & 31;
    const int wid  = tid >> 5;

    int nb = 0, sp = 0;
    if (tid < MOLSIZE) {
        sp = species[m * MOLSIZE + tid];
        ssp[tid] = sp;
        const float* cp = coords + (size_t)(m * MOLSIZE + tid) * 3;
        sc[tid] = make_float4(cp[0], cp[1], cp[2], 0.0f);
        nb = (sp > 0);
    }
    unsigned bal = __ballot_sync(0xffffffffu, nb);
    if (lane == 0) sW[wid] = __popc(bal);
    __syncthreads();

    const int nReal = g_nReal;
    if (tid < MOLSIZE) {
        int wbase = 0;
        #pragma unroll
        for (int w = 0; w < 4; w++) if (w < wid) wbase += sW[w];
        const int rank = g_atomBase[m] + wbase + __popc(bal & ((1u << lane) - 1u));
        srank[tid] = rank;
        if (nb) {
            out[3074 + rank]             = (float)sp;                                            // Z
            out[3074 + nReal + rank]     = (float)(tid * (MOLSIZE + 1) + m * MOLSIZE * MOLSIZE); // maskd
            out[3074 + 2 * nReal + rank] = (float)m;                                             // atom_molid
        }
    }
    __syncthreads();

    const int nP   = g_nPairs;
    const int base = g_pairBase[m];
    const int cnt  = g_pairCnt[m];
    const int P0   = 3074 + 3 * nReal;
    const unsigned short* pl = g_pairList + m * MAXP;

    for (int t = tid; t < cnt; t += 256) {
        const int ab = pl[t];
        const int a = ab >> 8, b = ab & 255;
        float4 pa = sc[a], pb = sc[b];
        float dx = pb.x - pa.x, dy = pb.y - pa.y, dz = pb.z - pa.z;
        float d2   = dx * dx + dy * dy + dz * dz;
        float dist = sqrtf(d2);
        const int q = base + t;
        out[P0 + q]           = (float)(m * (MOLSIZE * MOLSIZE) + a * MOLSIZE + b); // mask
        out[P0 + nP + q]      = (float)m;            // pair_molid
        out[P0 + 2 * nP + q]  = (float)ssp[a];       // ni
        out[P0 + 3 * nP + q]  = (float)ssp[b];       // nj
        out[P0 + 4 * nP + q]  = (float)srank[a];     // idxi
        out[P0 + 5 * nP + q]  = (float)srank[b];     // idxj
        out[P0 + 6 * nP + 3 * q + 0] = dx / dist;    // xij
        out[P0 + 6 * nP + 3 * q + 1] = dy / dist;
        out[P0 + 6 * nP + 3 * q + 2] = dz / dist;
        out[P0 + 9 * nP + q]  = dist * 1.8897261258369282f; // rij
    }
}

// ============================================================================
extern "C" void kernel_launch(void* const* d_in, const int* in_sizes, int n_in,
                              void* d_out, int out_size)
{
    const int*   species = (const int*)d_in[0];
    const float* coords  = (const float*)d_in[1];
    const float* tore    = (const float*)d_in[2];
    float*       out     = (float*)d_out;
    (void)in_sizes; (void)n_in; (void)out_size;

    k_count<<<CNT_GRID, 256>>>(species, coords, tore, out);
    k_write<<<NMOL, 256>>>(species, coords, out);
}

// round 4
// speedup vs baseline: 1.2750x; 1.0875x over previous
#include <cuda_runtime.h>

#define NMOL 1024
#define MOLSIZE 128
#define MAXP 8128          // 128*127/2 upper-triangle max per molecule

// ---- static device scratch (no runtime allocation allowed) ----
__device__ int            g_atomCnt[NMOL];
__device__ int            g_pairCnt[NMOL];
__device__ int            g_atomBase[NMOL];
__device__ int            g_pairBase[NMOL];
__device__ int            g_nReal;
__device__ int            g_nPairs;
__device__ int            g_ticket = 0;
__device__ int            g_atomInfo[NMOL * MOLSIZE];      // species | (localrank<<8)
__device__ unsigned short g_pairList[NMOL * MAXP];         // (a<<8)|b row-major per molecule

// d2 threshold replicating (sqrtf(d2) < 5.0f): largest excluded d2 is 25-1ulp.
__device__ __forceinline__ float d2_thresh() { return __int_as_float(0x41C7FFFF); }

// ============================================================================
// K1: one molecule per 256-thread block; each atom's 64-offset circular sweep
//     is split across two threads. Fused cross-molecule scan in last block.
// ============================================================================
__global__ void __launch_bounds__(256)
k_count(const int* __restrict__ species, const float* __restrict__ coords,
        const float* __restrict__ tore, float* __restrict__ out)
{
    __shared__ float4   sc[MOLSIZE];
    __shared__ unsigned rowmask[MOLSIZE][4];
    __shared__ unsigned nbw[4];
    __shared__ int      sWI[4][3];
    __shared__ float    sWF[4];
    __shared__ int      sWC[4];
    __shared__ int      sScanA[8], sScanB[8];
    __shared__ int      sLast;

    const int tid  = threadIdx.x;
    const int a    = tid & 127;
    const int half = tid >> 7;          // 0 or 1: offset-range split
    const int lane = tid & 31;
    const int wid  = tid >> 5;          // 0..7
    const int m    = blockIdx.x;

    // zero row masks (512 words, 2 per thread)
    ((unsigned*)rowmask)[tid]       = 0u;
    ((unsigned*)rowmask)[tid + 256] = 0u;

    int sp = 0;
    if (half == 0) {
        sp = species[m * MOLSIZE + a];
        const float* cp = coords + (size_t)(m * MOLSIZE + a) * 3;
        sc[a] = make_float4(cp[0], cp[1], cp[2], 0.0f);

        // stats (warps 0..3)
        int   h1 = (sp > 1), h2 = (sp == 1), h3 = (sp > 0);
        float f1 = tore[sp];
        #pragma unroll
        for (int o = 16; o; o >>= 1) {
            h1 += __shfl_down_sync(0xffffffffu, h1, o);
            h2 += __shfl_down_sync(0xffffffffu, h2, o);
            h3 += __shfl_down_sync(0xffffffffu, h3, o);
            f1 += __shfl_down_sync(0xffffffffu, f1, o);
        }
        if (lane == 0) { sWI[wid][0] = h1; sWI[wid][1] = h2; sWI[wid][2] = h3; sWF[wid] = f1; }
        const unsigned bal = __ballot_sync(0xffffffffu, sp > 0);
        if (lane == 0) nbw[wid] = bal;
    }
    __syncthreads();

    if (tid == 0) {
        int H = 0, Y = 0, N = 0; float F = 0.0f;
        #pragma unroll
        for (int w = 0; w < 4; w++) { H += sWI[w][0]; Y += sWI[w][1]; N += sWI[w][2]; F += sWF[w]; }
        out[2 + m]          = (float)H;               // nHeavy
        out[2 + NMOL + m]   = (float)Y;               // nHydro
        out[2 + 2*NMOL + m] = (float)(int)(F * 0.5f); // nocc
        g_atomCnt[m] = N;
        if (m == 0) { out[0] = (float)NMOL; out[1] = (float)MOLSIZE; }
    }

    // per-atom local rank among nonblank atoms -> g_atomInfo
    if (half == 0) {
        int wbase = 0;
        #pragma unroll
        for (int w = 0; w < 4; w++) if (w < wid) wbase += __popc(nbw[w]);
        const int lrank = wbase + __popc(nbw[wid] & ((1u << lane) - 1u));
        g_atomInfo[m * MOLSIZE + a] = sp | (lrank << 8);
    }

    const unsigned own = (nbw[a >> 5] >> (a & 31)) & 1u;
    const float4 me = sc[a];
    const float x = me.x, y = me.y, z = me.z;

    // ---- circular half-matrix distance tests, split across the two halves ----
    if (own) {
        const int oBeg = half ? 33 : 1;
        const int oEnd = half ? 64 : 33;           // [oBeg, oEnd)
        #pragma unroll 4
        for (int o = oBeg; o < oEnd; o++) {
            const int b = (a + o) & 127;
            float4 pb = sc[b];
            float dx = pb.x - x, dy = pb.y - y, dz = pb.z - z;
            float d2 = dx*dx + dy*dy + dz*dz;
            if (d2 < d2_thresh()) {
                const int i = a < b ? a : b;
                const int j = a ^ b ^ i;
                atomicOr(&rowmask[i][j >> 5], 1u << (j & 31));
            }
        }
        if (half && a < 64) {                      // o = 64 half-diagonal
            const int b = a + 64;
            float4 pb = sc[b];
            float dx = pb.x - x, dy = pb.y - y, dz = pb.z - z;
            float d2 = dx*dx + dy*dy + dz*dz;
            if (d2 < d2_thresh())
                atomicOr(&rowmask[a][b >> 5], 1u << (b & 31));
        }
    }
    __syncthreads();

    // ---- half 0: mask blanks, count, ordered scan, emit ----
    if (half == 0) {
        unsigned r[4];
        int cnt = 0;
        #pragma unroll
        for (int w = 0; w < 4; w++) {
            r[w] = own ? (rowmask[a][w] & nbw[w]) : 0u;
            cnt += __popc(r[w]);
        }
        int incl = cnt;
        #pragma unroll
        for (int o = 1; o < 32; o <<= 1) {
            int v = __shfl_up_sync(0xffffffffu, incl, o);
            if (lane >= o) incl += v;
        }
        if (lane == 31) sWC[wid] = incl;
        __syncwarp();
        // cross-warp bases (need all 4 warps' totals): barrier below shared by all
        __syncthreads();
        int wbase = 0;
        #pragma unroll
        for (int w = 0; w < 4; w++) if (w < wid) wbase += sWC[w];
        const int excl = wbase + incl - cnt;
        if (tid == 0) g_pairCnt[m] = sWC[0] + sWC[1] + sWC[2] + sWC[3];

        unsigned short* dst = g_pairList + m * MAXP + excl;
        int k = 0;
        #pragma unroll
        for (int w = 0; w < 4; w++) {
            unsigned mm = r[w];
            while (mm) {
                int b = (w << 5) + __ffs((int)mm) - 1;
                mm &= mm - 1u;
                dst[k++] = (unsigned short)((a << 8) | b);
            }
        }
    } else {
        __syncthreads();   // match half 0's barrier
    }

    // ---- fused global scan: last block to finish scans all 1024 counts ----
    __syncthreads();
    if (tid == 0) {
        __threadfence();
        int old = atomicAdd(&g_ticket, 1);
        sLast = (old == (int)gridDim.x - 1);
    }
    __syncthreads();
    if (sLast) {
        const int b4 = tid * 4;
        int oA[4], oB[4], sA = 0, sB = 0;
        #pragma unroll
        for (int q = 0; q < 4; q++) {
            oA[q] = g_atomCnt[b4 + q]; sA += oA[q];
            oB[q] = g_pairCnt[b4 + q]; sB += oB[q];
        }
        int ia = sA, ib = sB;
        #pragma unroll
        for (int o = 1; o < 32; o <<= 1) {
            int va = __shfl_up_sync(0xffffffffu, ia, o);
            int vb = __shfl_up_sync(0xffffffffu, ib, o);
            if (lane >= o) { ia += va; ib += vb; }
        }
        if (lane == 31) { sScanA[wid] = ia; sScanB[wid] = ib; }
        __syncthreads();
        int bA = 0, bB = 0;
        #pragma unroll
        for (int w = 0; w < 8; w++) if (w < wid) { bA += sScanA[w]; bB += sScanB[w]; }
        int pA = bA + ia - sA, pB = bB + ib - sB;
        #pragma unroll
        for (int q = 0; q < 4; q++) {
            g_atomBase[b4 + q] = pA; pA += oA[q];
            g_pairBase[b4 + q] = pB; pB += oB[q];
        }
        if (tid == 255) { g_nReal = pA; g_nPairs = pB; }
        if (tid == 0)   g_ticket = 0;    // reset for next graph replay
    }
}

// ============================================================================
// K2: scatter outputs; 2 molecules per 256-thread block
// ============================================================================
__global__ void __launch_bounds__(256)
k_write(const float* __restrict__ coords, float* __restrict__ out)
{
    __shared__ float4 sc[2][MOLSIZE];
    __shared__ short  ssp[2][MOLSIZE];
    __shared__ int    srank[2][MOLSIZE];

    const int tid = threadIdx.x;
    const int ml  = tid >> 7;
    const int a   = tid & 127;
    const int m0  = blockIdx.x * 2;
    const int m   = m0 + ml;

    const int nReal = g_nReal;
    const int nP    = g_nPairs;
    const int P0    = 3074 + 3 * nReal;

    {
        const int info  = g_atomInfo[m * MOLSIZE + a];
        const int sp    = info & 255;
        const int rank  = g_atomBase[m] + (info >> 8);
        const float* cp = coords + (size_t)(m * MOLSIZE + a) * 3;
        sc[ml][a]   = make_float4(cp[0], cp[1], cp[2], 0.0f);
        ssp[ml][a]  = (short)sp;
        srank[ml][a] = rank;
        if (sp > 0) {
            out[3074 + rank]             = (float)sp;                                          // Z
            out[3074 + nReal + rank]     = (float)(a * (MOLSIZE + 1) + m * MOLSIZE * MOLSIZE); // maskd
            out[3074 + 2 * nReal + rank] = (float)m;                                           // atom_molid
        }
    }
    __syncthreads();

    #pragma unroll
    for (int mm = 0; mm < 2; mm++) {
        const int mol  = m0 + mm;
        const int base = g_pairBase[mol];
        const int cnt  = g_pairCnt[mol];
        const unsigned short* pl = g_pairList + mol * MAXP;
        const float molf = (float)mol;
        const float mbase = (float)(mol * (MOLSIZE * MOLSIZE));

        for (int t = tid; t < cnt; t += 256) {
            const int ab = pl[t];
            const int a2 = ab >> 8, b2 = ab & 255;
            float4 pa = sc[mm][a2], pb = sc[mm][b2];
            float dx = pb.x - pa.x, dy = pb.y - pa.y, dz = pb.z - pa.z;
            float d2  = dx * dx + dy * dy + dz * dz;
            float inv = rsqrtf(d2);
            float dist = d2 * inv;
            const int q = base + t;
            out[P0 + q]          = mbase + (float)(a2 * MOLSIZE + b2);   // mask
            out[P0 + nP + q]     = molf;                                 // pair_molid
            out[P0 + 2*nP + q]   = (float)ssp[mm][a2];                   // ni
            out[P0 + 3*nP + q]   = (float)ssp[mm][b2];                   // nj
            out[P0 + 4*nP + q]   = (float)srank[mm][a2];                 // idxi
            out[P0 + 5*nP + q]   = (float)srank[mm][b2];                 // idxj
            out[P0 + 6*nP + 3*q + 0] = dx * inv;                         // xij
            out[P0 + 6*nP + 3*q + 1] = dy * inv;
            out[P0 + 6*nP + 3*q + 2] = dz * inv;
            out[P0 + 9*nP + q]   = dist * 1.8897261258369282f;           // rij
        }
    }
}

// ============================================================================
extern "C" void kernel_launch(void* const* d_in, const int* in_sizes, int n_in,
                              void* d_out, int out_size)
{
    const int*   species = (const int*)d_in[0];
    const float* coords  = (const float*)d_in[1];
    const float* tore    = (const float*)d_in[2];
    float*       out     = (float*)d_out;
    (void)in_sizes; (void)n_in; (void)out_size;

    k_count<<<NMOL, 256>>>(species, coords, tore, out);
    k_write<<<NMOL / 2, 256>>>(coords, out);
}